// round 2
// baseline (speedup 1.0000x reference)
#include <cuda_runtime.h>
#include <cuda_bf16.h>
#include <math.h>

// ---------------------------------------------------------------------------
// Problem constants
// ---------------------------------------------------------------------------
#define BATCH   32
#define TOK     197          // 1 cls + 196 patches
#define NPATCH  196
#define DIM     768
#define HEADS   12
#define DH      64
#define QKVDIM  2304
#define FF      3072
#define DEPTH   12
#define MROWS   (BATCH*TOK)      // 6304
#define MPATCH  (BATCH*NPATCH)   // 6272

// ---------------------------------------------------------------------------
// Device scratch (static globals; no allocation allowed)
// ---------------------------------------------------------------------------
__device__ float g_wqkv[DEPTH*DIM*QKVDIM];       // quantized Wqkv
__device__ float g_wo  [DEPTH*DIM*DIM];          // quantized Wo
__device__ float g_w1  [11*DIM*FF];              // quantized W1 (layers 0..10)
__device__ float g_w2  [11*FF*DIM];              // quantized W2 (layers 0..10)
__device__ float g_x   [MROWS*DIM];
__device__ float g_h   [MROWS*DIM];
__device__ float g_qkv [MROWS*QKVDIM];
__device__ float g_o   [MROWS*DIM];
__device__ float g_mlp [MROWS*FF];

// radix-select / quantization state
__device__ unsigned int        g_hist[256];
__device__ unsigned int        g_prefix;
__device__ unsigned long long  g_rank;
__device__ double              g_part[512];
__device__ float               g_scale_v;
__device__ float               g_thr_v;
__device__ unsigned long long  g_cntle;
__device__ unsigned int        g_mingt;

// ---------------------------------------------------------------------------
// Ternary quantization: exact median of |W| via radix select on float bits
// ---------------------------------------------------------------------------
__global__ void sel_init(unsigned long long k0) {
    g_hist[threadIdx.x] = 0u;
    if (threadIdx.x == 0) { g_prefix = 0u; g_rank = k0; }
}

__global__ void __launch_bounds__(256) sel_hist(const float* __restrict__ w, int n, int shift) {
    __shared__ unsigned int h[256];
    __shared__ float red[256];
    h[threadIdx.x] = 0u;
    __syncthreads();
    unsigned mask = (shift == 24) ? 0u : (0xFFFFFFFFu << (shift + 8));
    unsigned pref = g_prefix & mask;
    float ls = 0.f;
    int stride = gridDim.x * blockDim.x;
    for (int i = blockIdx.x * blockDim.x + threadIdx.x; i < n; i += stride) {
        unsigned bits = __float_as_uint(w[i]) & 0x7FFFFFFFu;
        if (shift == 24) ls += __uint_as_float(bits);
        if ((bits & mask) == pref) atomicAdd(&h[(bits >> shift) & 0xFFu], 1u);
    }
    __syncthreads();
    atomicAdd(&g_hist[threadIdx.x], h[threadIdx.x]);
    if (shift == 24) {
        red[threadIdx.x] = ls;
        __syncthreads();
        for (int s = 128; s > 0; s >>= 1) {
            if (threadIdx.x < s) red[threadIdx.x] += red[threadIdx.x + s];
            __syncthreads();
        }
        if (threadIdx.x == 0) g_part[blockIdx.x] = (double)red[0];
    }
}

__global__ void sel_scan(int shift, int n) {
    if (shift == 24) {
        double s = 0.0;
        for (int i = 0; i < 512; i++) s += g_part[i];
        g_scale_v = (float)(s / (double)n);
    }
    unsigned long long r = g_rank, cum = 0ull, cumBefore = 0ull;
    int bin = -1;
    for (int i = 0; i < 256; i++) {
        unsigned c = g_hist[i];
        g_hist[i] = 0u;
        if (bin < 0) {
            if (cum + c > r) { bin = i; cumBefore = cum; }
            else cum += c;
        }
    }
    if (bin < 0) bin = 255;  // should not happen
    g_prefix |= ((unsigned)bin) << shift;
    g_rank = r - cumBefore;
    if (shift == 0) { g_cntle = 0ull; g_mingt = 0x7FFFFFFFu; }
}

__global__ void __launch_bounds__(256) sel_pass2(const float* __restrict__ w, int n) {
    __shared__ unsigned long long cr[256];
    __shared__ unsigned int mr[256];
    unsigned v1 = g_prefix;
    unsigned long long lc = 0ull;
    unsigned lm = 0x7FFFFFFFu;
    int stride = gridDim.x * blockDim.x;
    for (int i = blockIdx.x * blockDim.x + threadIdx.x; i < n; i += stride) {
        unsigned bits = __float_as_uint(w[i]) & 0x7FFFFFFFu;
        if (bits <= v1) lc++;
        else lm = min(lm, bits);
    }
    cr[threadIdx.x] = lc; mr[threadIdx.x] = lm;
    __syncthreads();
    for (int s = 128; s > 0; s >>= 1) {
        if (threadIdx.x < s) {
            cr[threadIdx.x] += cr[threadIdx.x + s];
            mr[threadIdx.x] = min(mr[threadIdx.x], mr[threadIdx.x + s]);
        }
        __syncthreads();
    }
    if (threadIdx.x == 0) {
        atomicAdd(&g_cntle, cr[0]);
        atomicMin(&g_mingt, mr[0]);
    }
}

__global__ void sel_fin(unsigned long long k0) {
    float v1 = __uint_as_float(g_prefix);
    float v2 = (g_cntle >= k0 + 2ull) ? v1 : __uint_as_float(g_mingt);
    g_thr_v = 0.5f * v1 + 0.5f * v2;   // linear interpolation at q=0.5 on even N
}

__global__ void __launch_bounds__(256) quant_k(const float* __restrict__ w, float* __restrict__ q, int n) {
    int i = blockIdx.x * blockDim.x + threadIdx.x;
    if (i >= n) return;
    float thr = g_thr_v, sc = g_scale_v;
    float x = w[i];
    float a = fabsf(x);
    float s = (x > 0.f) ? sc : ((x < 0.f) ? -sc : 0.f);
    q[i] = (a >= thr) ? s : 0.f;
}

// ---------------------------------------------------------------------------
// Patchify: img [32,3,224,224] -> [32,196,768] with d = (p1*16+p2)*3 + c
// ---------------------------------------------------------------------------
__global__ void patchify_k(const float* __restrict__ img, float* __restrict__ out) {
    int idx = blockIdx.x * 256 + threadIdx.x;
    if (idx >= MPATCH * DIM) return;
    int d = idx % DIM;
    int t = (idx / DIM) % NPATCH;
    int b = idx / (DIM * NPATCH);
    int c  = d % 3;
    int p  = d / 3;
    int p1 = p >> 4, p2 = p & 15;
    int hh = t / 14, ww = t % 14;
    out[idx] = img[(((long long)b * 3 + c) * 224 + (hh * 16 + p1)) * 224 + (ww * 16 + p2)];
}

// ---------------------------------------------------------------------------
// Assemble: x[b,0,:] = cls+pos[0]; x[b,1+t,:] = emb[b,t,:]+pos[1+t]
// ---------------------------------------------------------------------------
__global__ void assemble_k(const float* __restrict__ emb, const float* __restrict__ cls,
                           const float* __restrict__ pos, float* __restrict__ x) {
    int idx = blockIdx.x * 256 + threadIdx.x;
    if (idx >= MROWS * DIM) return;
    int d = idx % DIM;
    int t = (idx / DIM) % TOK;
    int b = idx / (DIM * TOK);
    float v;
    if (t == 0) v = cls[d] + pos[d];
    else        v = emb[((long long)b * NPATCH + (t - 1)) * DIM + d] + pos[(long long)t * DIM + d];
    x[idx] = v;
}

// ---------------------------------------------------------------------------
// LayerNorm over last dim (768). One block per row, 256 threads.
// ---------------------------------------------------------------------------
__global__ void __launch_bounds__(256) ln_k(const float* __restrict__ in, const float* __restrict__ gam,
                                            const float* __restrict__ bet, float* __restrict__ out) {
    __shared__ float red[256];
    long long row = blockIdx.x;
    const float* x = in + row * DIM;
    int tid = threadIdx.x;
    float v0 = x[tid], v1 = x[tid + 256], v2 = x[tid + 512];
    red[tid] = v0 + v1 + v2;
    __syncthreads();
    for (int s = 128; s > 0; s >>= 1) {
        if (tid < s) red[tid] += red[tid + s];
        __syncthreads();
    }
    float mean = red[0] * (1.f / 768.f);
    __syncthreads();
    float d0 = v0 - mean, d1 = v1 - mean, d2 = v2 - mean;
    red[tid] = d0 * d0 + d1 * d1 + d2 * d2;
    __syncthreads();
    for (int s = 128; s > 0; s >>= 1) {
        if (tid < s) red[tid] += red[tid + s];
        __syncthreads();
    }
    float inv = rsqrtf(red[0] * (1.f / 768.f) + 1e-5f);
    float* o = out + row * DIM;
    o[tid]       = d0 * inv * gam[tid]       + bet[tid];
    o[tid + 256] = d1 * inv * gam[tid + 256] + bet[tid + 256];
    o[tid + 512] = d2 * inv * gam[tid + 512] + bet[tid + 512];
}

// ---------------------------------------------------------------------------
// SGEMM: C[M,N] = A[M,K] @ B[K,N] + bias (+residual / gelu epilogue)
// BM=BN=128, BK=8, TM=TN=8, 256 threads. Requires N%128==0, K%8==0.
// ---------------------------------------------------------------------------
#define MODE_STORE 0
#define MODE_RESID 1
#define MODE_GELU  2

template<int MODE>
__global__ void __launch_bounds__(256) sgemm_k(const float* __restrict__ A,
                                               const float* __restrict__ B,
                                               const float* __restrict__ bias,
                                               const float* __restrict__ R,
                                               float* __restrict__ C,
                                               int M, int N, int K) {
    __shared__ float As[8][128];
    __shared__ float Bs[8][128];
    int tid = threadIdx.x;
    int row0 = blockIdx.y * 128;
    int col0 = blockIdx.x * 128;
    int arow = tid >> 1;
    int acol = (tid & 1) * 4;
    int brow = tid >> 5;
    int bcol = (tid & 31) * 4;
    int ty = tid >> 4, tx = tid & 15;

    float acc[8][8];
    #pragma unroll
    for (int i = 0; i < 8; i++)
        #pragma unroll
        for (int j = 0; j < 8; j++) acc[i][j] = 0.f;

    for (int k0 = 0; k0 < K; k0 += 8) {
        float4 av;
        int gr = row0 + arow;
        if (gr < M) av = *reinterpret_cast<const float4*>(A + (long long)gr * K + k0 + acol);
        else        av = make_float4(0.f, 0.f, 0.f, 0.f);
        As[acol + 0][arow] = av.x;
        As[acol + 1][arow] = av.y;
        As[acol + 2][arow] = av.z;
        As[acol + 3][arow] = av.w;
        float4 bv = *reinterpret_cast<const float4*>(B + (long long)(k0 + brow) * N + col0 + bcol);
        *reinterpret_cast<float4*>(&Bs[brow][bcol]) = bv;
        __syncthreads();
        #pragma unroll
        for (int k = 0; k < 8; k++) {
            float ra[8], rb[8];
            #pragma unroll
            for (int i = 0; i < 8; i++) ra[i] = As[k][ty * 8 + i];
            #pragma unroll
            for (int j = 0; j < 8; j++) rb[j] = Bs[k][tx * 8 + j];
            #pragma unroll
            for (int i = 0; i < 8; i++)
                #pragma unroll
                for (int j = 0; j < 8; j++) acc[i][j] += ra[i] * rb[j];
        }
        __syncthreads();
    }

    #pragma unroll
    for (int i = 0; i < 8; i++) {
        int r = row0 + ty * 8 + i;
        if (r >= M) continue;
        long long base = (long long)r * N + col0 + tx * 8;
        #pragma unroll
        for (int j = 0; j < 8; j++) {
            float v = acc[i][j] + bias[col0 + tx * 8 + j];
            if (MODE == MODE_RESID) v += R[base + j];
            if (MODE == MODE_GELU) {
                float xx = v;
                v = 0.5f * xx * (1.f + tanhf(0.7978845608028654f * (xx + 0.044715f * xx * xx * xx)));
            }
            C[base + j] = v;
        }
    }
}

// ---------------------------------------------------------------------------
// Attention: one CTA per (head, batch). K,V staged in smem (stride 65).
// ---------------------------------------------------------------------------
#define KV_STRIDE 65
#define KS_FLOATS (TOK * KV_STRIDE)
#define ATTN_SMEM_FLOATS (2 * KS_FLOATS + 8 * 64 + 8 * 200)
#define ATTN_SMEM_BYTES  (ATTN_SMEM_FLOATS * 4)

__global__ void __launch_bounds__(256) attn_k(const float* __restrict__ qkv, float* __restrict__ o) {
    extern __shared__ float sm[];
    float* ks = sm;
    float* vs = ks + KS_FLOATS;
    float* qs = vs + KS_FLOATS;        // 8*64
    float* ps = qs + 8 * 64;           // 8*200

    int h = blockIdx.x, b = blockIdx.y;
    int tid = threadIdx.x, lane = tid & 31, w = tid >> 5;
    const long long rowbase = (long long)b * TOK * QKVDIM;
    const int hoff = h * DH;

    for (int idx = tid; idx < TOK * DH; idx += 256) {
        int j = idx >> 6, d = idx & 63;
        long long src = rowbase + (long long)j * QKVDIM + hoff + d;
        ks[j * KV_STRIDE + d] = qkv[src + DIM];
        vs[j * KV_STRIDE + d] = qkv[src + 2 * DIM];
    }
    __syncthreads();

    for (int i = w; i < TOK; i += 8) {
        long long qoff = rowbase + (long long)i * QKVDIM + hoff;
        qs[w * 64 + lane]      = qkv[qoff + lane];
        qs[w * 64 + 32 + lane] = qkv[qoff + 32 + lane];
        __syncwarp();

        float s[7];
        #pragma unroll
        for (int t = 0; t < 7; t++) {
            int j = lane + 32 * t;
            float a = -1e30f;
            if (j < TOK) {
                a = 0.f;
                const float* kr = ks + j * KV_STRIDE;
                const float* qr = qs + w * 64;
                #pragma unroll
                for (int d = 0; d < 64; d++) a += qr[d] * kr[d];
                a *= 0.125f;
            }
            s[t] = a;
        }
        float m = s[0];
        #pragma unroll
        for (int t = 1; t < 7; t++) m = fmaxf(m, s[t]);
        #pragma unroll
        for (int off = 16; off; off >>= 1) m = fmaxf(m, __shfl_xor_sync(0xffffffffu, m, off));
        float sum = 0.f;
        #pragma unroll
        for (int t = 0; t < 7; t++) { s[t] = expf(s[t] - m); sum += s[t]; }
        #pragma unroll
        for (int off = 16; off; off >>= 1) sum += __shfl_xor_sync(0xffffffffu, sum, off);
        float inv = 1.f / sum;
        #pragma unroll
        for (int t = 0; t < 7; t++) {
            int j = lane + 32 * t;
            if (j < TOK) ps[w * 200 + j] = s[t] * inv;
        }
        __syncwarp();

        float a0 = 0.f, a1 = 0.f;
        for (int j = 0; j < TOK; j++) {
            float pj = ps[w * 200 + j];
            a0 += pj * vs[j * KV_STRIDE + lane];
            a1 += pj * vs[j * KV_STRIDE + 32 + lane];
        }
        long long obase = ((long long)b * TOK + i) * DIM + hoff;
        o[obase + lane]      = a0;
        o[obase + 32 + lane] = a1;
        __syncwarp();
    }
}

// ---------------------------------------------------------------------------
// Host orchestration
// ---------------------------------------------------------------------------
static void ternary_quant(const float* w, float* q, int n) {
    unsigned long long k0 = (unsigned long long)(n / 2 - 1);
    sel_init<<<1, 256>>>(k0);
    for (int r = 0; r < 4; r++) {
        int shift = 24 - 8 * r;
        sel_hist<<<512, 256>>>(w, n, shift);
        sel_scan<<<1, 1>>>(shift, n);
    }
    sel_pass2<<<512, 256>>>(w, n);
    sel_fin<<<1, 1>>>(k0);
    quant_k<<<(n + 255) / 256, 256>>>(w, q, n);
}

extern "C" void kernel_launch(void* const* d_in, const int* in_sizes, int n_in,
                              void* d_out, int out_size) {
    const float* img        = (const float*)d_in[0];
    const float* patch_ln_g = (const float*)d_in[1];
    const float* patch_ln_b = (const float*)d_in[2];
    const float* W_patch    = (const float*)d_in[3];
    const float* b_patch    = (const float*)d_in[4];
    const float* emb_ln_g   = (const float*)d_in[5];
    const float* emb_ln_b   = (const float*)d_in[6];
    const float* pos_emb    = (const float*)d_in[7];
    const float* cls_token  = (const float*)d_in[8];
    const float* ln1_g      = (const float*)d_in[9];
    const float* ln1_b      = (const float*)d_in[10];
    const float* Wqkv       = (const float*)d_in[11];
    const float* b_qkv      = (const float*)d_in[12];
    const float* Wo         = (const float*)d_in[13];
    const float* b_o        = (const float*)d_in[14];
    const float* ln2_g      = (const float*)d_in[15];
    const float* ln2_b      = (const float*)d_in[16];
    const float* W1         = (const float*)d_in[17];
    const float* b1         = (const float*)d_in[18];
    const float* W2         = (const float*)d_in[19];
    const float* b2         = (const float*)d_in[20];
    const float* norm_g     = (const float*)d_in[21];
    const float* norm_b     = (const float*)d_in[22];

    float *wq, *wo, *w1q, *w2q, *X, *H, *QKV, *O, *MLP;
    cudaGetSymbolAddress((void**)&wq,  g_wqkv);
    cudaGetSymbolAddress((void**)&wo,  g_wo);
    cudaGetSymbolAddress((void**)&w1q, g_w1);
    cudaGetSymbolAddress((void**)&w2q, g_w2);
    cudaGetSymbolAddress((void**)&X,   g_x);
    cudaGetSymbolAddress((void**)&H,   g_h);
    cudaGetSymbolAddress((void**)&QKV, g_qkv);
    cudaGetSymbolAddress((void**)&O,   g_o);
    cudaGetSymbolAddress((void**)&MLP, g_mlp);

    cudaFuncSetAttribute(attn_k, cudaFuncAttributeMaxDynamicSharedMemorySize, ATTN_SMEM_BYTES);

    // --- ternary-quantize all weights (layers 0..10 for FF; all 12 for attn) ---
    for (int i = 0; i < DEPTH; i++)
        ternary_quant(Wqkv + (long long)i * DIM * QKVDIM, wq + (long long)i * DIM * QKVDIM, DIM * QKVDIM);
    for (int i = 0; i < DEPTH; i++)
        ternary_quant(Wo + (long long)i * DIM * DIM, wo + (long long)i * DIM * DIM, DIM * DIM);
    for (int i = 0; i < DEPTH - 1; i++)
        ternary_quant(W1 + (long long)i * DIM * FF, w1q + (long long)i * DIM * FF, DIM * FF);
    for (int i = 0; i < DEPTH - 1; i++)
        ternary_quant(W2 + (long long)i * FF * DIM, w2q + (long long)i * FF * DIM, FF * DIM);

    // --- patch embedding ---
    patchify_k<<<(MPATCH * DIM + 255) / 256, 256>>>(img, H);
    ln_k<<<MPATCH, 256>>>(H, patch_ln_g, patch_ln_b, O);
    sgemm_k<MODE_STORE><<<dim3(DIM / 128, (MPATCH + 127) / 128), 256>>>(O, W_patch, b_patch, nullptr, H, MPATCH, DIM, DIM);
    ln_k<<<MPATCH, 256>>>(H, emb_ln_g, emb_ln_b, O);
    assemble_k<<<(MROWS * DIM + 255) / 256, 256>>>(O, cls_token, pos_emb, X);

    // --- transformer layers ---
    for (int i = 0; i < DEPTH; i++) {
        ln_k<<<MROWS, 256>>>(X, ln1_g + i * DIM, ln1_b + i * DIM, H);
        sgemm_k<MODE_STORE><<<dim3(QKVDIM / 128, (MROWS + 127) / 128), 256>>>(
            H, wq + (long long)i * DIM * QKVDIM, b_qkv + i * QKVDIM, nullptr, QKV, MROWS, QKVDIM, DIM);
        attn_k<<<dim3(HEADS, BATCH), 256, ATTN_SMEM_BYTES>>>(QKV, O);
        sgemm_k<MODE_RESID><<<dim3(DIM / 128, (MROWS + 127) / 128), 256>>>(
            O, wo + (long long)i * DIM * DIM, b_o + i * DIM, X, X, MROWS, DIM, DIM);
        ln_k<<<MROWS, 256>>>(X, ln2_g + i * DIM, ln2_b + i * DIM, H);
        const float* w1p = (i < DEPTH - 1) ? (w1q + (long long)i * DIM * FF) : (W1 + (long long)(DEPTH - 1) * DIM * FF);
        const float* w2p = (i < DEPTH - 1) ? (w2q + (long long)i * FF * DIM) : (W2 + (long long)(DEPTH - 1) * FF * DIM);
        sgemm_k<MODE_GELU><<<dim3(FF / 128, (MROWS + 127) / 128), 256>>>(
            H, w1p, b1 + i * FF, nullptr, MLP, MROWS, FF, DIM);
        sgemm_k<MODE_RESID><<<dim3(DIM / 128, (MROWS + 127) / 128), 256>>>(
            MLP, w2p, b2 + i * DIM, X, X, MROWS, DIM, FF);
    }

    // --- final layernorm into output ---
    ln_k<<<MROWS, 256>>>(X, norm_g, norm_b, (float*)d_out);
}